// round 6
// baseline (speedup 1.0000x reference)
#include <cuda_runtime.h>
#include <cuda_fp16.h>
#include <cstdint>

#define THREADS 512
// ---- shared memory layout (bytes) ----
#define WS8_OFF   0                       // B~ frags: 32j*4kc*4nb*32ln*4B = 65536
#define WH_OFF    65536                   // W_lin hi fp16 frags: 4kc*4nb*32*4 = 2048
#define WL_OFF    67584                   // W_lin lo fp16 frags: 2048
#define XT_OFF    69632                   // two x tiles, 512 rows * 36 floats
#define XT_STRIDE 36
#define XT_BYTES  (512 * XT_STRIDE * 4)   // 73728
#define SMEM_BYTES (XT_OFF + 2 * XT_BYTES) // 217088

static __device__ __forceinline__ uint32_t smem_u32(const void* p) {
    uint32_t a;
    asm("{ .reg .u64 t; cvta.to.shared.u64 t, %1; cvt.u32.u64 %0, t; }" : "=r"(a) : "l"(p));
    return a;
}
// splat fp32 -> {h,h} packed fp16x2
static __device__ __forceinline__ uint32_t hsplat(float f) {
    uint32_t d; asm("cvt.rn.f16x2.f32 %0, %1, %1;" : "=r"(d) : "f"(f)); return d;
}
static __device__ __forceinline__ uint32_t hmul2(uint32_t a, uint32_t b) {
    uint32_t d; asm("mul.rn.f16x2 %0, %1, %2;" : "=r"(d) : "r"(a), "r"(b)); return d;
}
static __device__ __forceinline__ uint32_t hpack(float lo, float hi) {
    __half2 h = __floats2half2_rn(lo, hi);
    return *reinterpret_cast<uint32_t*>(&h);
}
// split float2 into fp16 hi + fp16 residual (packed)
static __device__ __forceinline__ void hsplit(float2 v, uint32_t& h, uint32_t& l) {
    __half2 hh = __floats2half2_rn(v.x, v.y);
    float2 b = __half22float2(hh);
    __half2 ll = __floats2half2_rn(v.x - b.x, v.y - b.y);
    h = *reinterpret_cast<uint32_t*>(&hh);
    l = *reinterpret_cast<uint32_t*>(&ll);
}
// f16 m16n8k8: D += A*B, fp32 accum. A = 2 regs, B = 1 reg.
static __device__ __forceinline__ void mma8h(float* acc, uint32_t a0, uint32_t a1, uint32_t b) {
    asm volatile(
        "mma.sync.aligned.m16n8k8.row.col.f32.f16.f16.f32 "
        "{%0,%1,%2,%3}, {%4,%5}, {%6}, {%0,%1,%2,%3};"
        : "+f"(acc[0]), "+f"(acc[1]), "+f"(acc[2]), "+f"(acc[3])
        : "r"(a0), "r"(a1), "r"(b));
}

#define CP_ASYNC16(dst, src) \
    asm volatile("cp.async.cg.shared.global [%0], [%1], 16;" :: "r"(dst), "l"(src) : "memory")
#define CP_COMMIT() asm volatile("cp.async.commit_group;" ::: "memory")
#define CP_WAIT1()  asm volatile("cp.async.wait_group 1;" ::: "memory")
#define CP_WAIT0()  asm volatile("cp.async.wait_group 0;" ::: "memory")

extern __shared__ __align__(1024) char smem[];

__global__ void __launch_bounds__(THREADS, 1)
nnode_kernel(const float* __restrict__ x, const float* __restrict__ wlin,
             const float* __restrict__ wnl, float* __restrict__ out, int ntiles) {
    const uint32_t sb = smem_u32(smem);
    const int tid  = threadIdx.x;
    const int wid  = tid >> 5;
    const int lane = tid & 31;
    const int q    = lane & 3;
    const int g    = lane >> 2;
    const int grid = gridDim.x;

    // ===== build symmetrized-triangle fp16 W_nl B~ fragments =====
    // ws8[((j*4+kc)*4+nb)*32 + ln] = pack( c*(W[n,i0,j]+W[n,j,i0]),
    //                                      c*(W[n,i0+1,j]+W[n,j,i0+1]) )
    //   n = nb*8+(ln>>2), i0 = kc*8+2*(ln&3), jc = j>>3
    //   c = 1 for kc<jc (off-diag doubled), 0.5 for kc==jc, (kc>jc never read)
    {
        uint32_t* ws = reinterpret_cast<uint32_t*>(smem + WS8_OFF);
        for (int idx = tid; idx < 16384; idx += THREADS) {
            int j  = idx >> 9;
            int kc = (idx >> 7) & 3;
            int nb = (idx >> 5) & 3;
            int ln = idx & 31;
            int n  = nb * 8 + (ln >> 2);
            int i0 = kc * 8 + 2 * (ln & 3);
            int jc = j >> 3;
            float c = (kc < jc) ? 1.0f : 0.5f;
            const float* wn = wnl + n * 1024;
            float v0 = c * (__ldg(wn + i0 * 32 + j)       + __ldg(wn + j * 32 + i0));
            float v1 = c * (__ldg(wn + (i0 + 1) * 32 + j) + __ldg(wn + j * 32 + i0 + 1));
            ws[idx] = hpack(v0, v1);
        }
    }
    // ===== W_lin hi/lo fp16 fragments =====
    {
        uint32_t* wh = reinterpret_cast<uint32_t*>(smem + WH_OFF);
        uint32_t* wl = reinterpret_cast<uint32_t*>(smem + WL_OFF);
        for (int idx = tid; idx < 512; idx += THREADS) {
            int kc = idx >> 7;
            int nb = (idx >> 5) & 3;
            int ln = idx & 31;
            int n  = nb * 8 + (ln >> 2);
            int i0 = kc * 8 + 2 * (ln & 3);
            float2 v = make_float2(__ldg(wlin + i0 * 32 + n), __ldg(wlin + (i0 + 1) * 32 + n));
            uint32_t h, l;
            hsplit(v, h, l);
            wh[idx] = h; wl[idx] = l;
        }
    }

    // ===== prefetch first 512-row x tile (16384 floats = 512thr*4*8) =====
    const int t0 = blockIdx.x;
    if (t0 < ntiles) {
        const float* src = x + (size_t)t0 * 16384;
        #pragma unroll
        for (int s = 0; s < 8; ++s) {
            int f = (tid + s * THREADS) * 4;
            int r = f >> 5, c = f & 31;
            CP_ASYNC16(sb + XT_OFF + (uint32_t)(r * XT_STRIDE + c) * 4, src + f);
        }
    }
    CP_COMMIT();

    const int rA = wid * 32 + g;                  // warp owns rows [wid*32, wid*32+32)
    const uint32_t* wsp = reinterpret_cast<const uint32_t*>(smem + WS8_OFF) + lane;
    const uint32_t* whp = reinterpret_cast<const uint32_t*>(smem + WH_OFF) + lane;
    const uint32_t* wlp = reinterpret_cast<const uint32_t*>(smem + WL_OFF) + lane;

    int buf = 0;
    for (int t = t0; t < ntiles; t += grid) {
        __syncthreads();
        int tn = t + grid;
        if (tn < ntiles) {
            const float* src = x + (size_t)tn * 16384;
            uint32_t dst = sb + XT_OFF + (uint32_t)(buf ^ 1) * XT_BYTES;
            #pragma unroll
            for (int s = 0; s < 8; ++s) {
                int f = (tid + s * THREADS) * 4;
                int r = f >> 5, c = f & 31;
                CP_ASYNC16(dst + (uint32_t)(r * XT_STRIDE + c) * 4, src + f);
            }
            CP_COMMIT();
            CP_WAIT1();
        } else {
            CP_WAIT0();
        }
        __syncthreads();

        const float* xt  = reinterpret_cast<const float*>(smem + XT_OFF + buf * XT_BYTES);
        const float* xr0 = xt + (rA +  0) * XT_STRIDE;
        const float* xr1 = xt + (rA +  8) * XT_STRIDE;
        const float* xr2 = xt + (rA + 16) * XT_STRIDE;
        const float* xr3 = xt + (rA + 24) * XT_STRIDE;

        // ---- packed fp16 hi (xp8) + residual (xlp8) X fragments ----
        // xp8[kc][ridx] = {x[r,2q+8kc], x[r,2q+1+8kc]} as fp16x2, r = rA+8*ridx
        uint32_t xp8[4][4], xlp8[4][4];
        #pragma unroll
        for (int kc = 0; kc < 4; ++kc) {
            hsplit(*reinterpret_cast<const float2*>(xr0 + kc * 8 + 2 * q), xp8[kc][0], xlp8[kc][0]);
            hsplit(*reinterpret_cast<const float2*>(xr1 + kc * 8 + 2 * q), xp8[kc][1], xlp8[kc][1]);
            hsplit(*reinterpret_cast<const float2*>(xr2 + kc * 8 + 2 * q), xp8[kc][2], xlp8[kc][2]);
            hsplit(*reinterpret_cast<const float2*>(xr3 + kc * 8 + 2 * q), xp8[kc][3], xlp8[kc][3]);
        }

        float acc[2][4][4];
        #pragma unroll
        for (int f = 0; f < 2; ++f)
            #pragma unroll
            for (int nb = 0; nb < 4; ++nb)
                #pragma unroll
                for (int e = 0; e < 4; ++e) acc[f][nb][e] = 0.f;

        // ---- linear term: fp16 3-split (xh@Wh + xl@Wh + xh@Wl), exact products ----
        #pragma unroll
        for (int kc = 0; kc < 4; ++kc) {
            #pragma unroll
            for (int nb = 0; nb < 4; ++nb) {
                uint32_t bh = whp[(kc * 4 + nb) * 32];
                uint32_t bl = wlp[(kc * 4 + nb) * 32];
                mma8h(acc[0][nb], xp8[kc][0],  xp8[kc][1],  bh);
                mma8h(acc[0][nb], xlp8[kc][0], xlp8[kc][1], bh);
                mma8h(acc[0][nb], xp8[kc][0],  xp8[kc][1],  bl);
                mma8h(acc[1][nb], xp8[kc][2],  xp8[kc][3],  bh);
                mma8h(acc[1][nb], xlp8[kc][2], xlp8[kc][3], bh);
                mma8h(acc[1][nb], xp8[kc][2],  xp8[kc][3],  bl);
            }
        }

        // ---- bilinear: symmetrized triangle, only i-chunks kc <= jc ----
        #pragma unroll
        for (int jc = 0; jc < 4; ++jc) {
            #pragma unroll 4
            for (int jj = 0; jj < 8; ++jj) {
                const int j = jc * 8 + jj;
                uint32_t s0 = hsplat(xr0[j]);
                uint32_t s1 = hsplat(xr1[j]);
                uint32_t s2 = hsplat(xr2[j]);
                uint32_t s3 = hsplat(xr3[j]);
                #pragma unroll
                for (int kc = 0; kc <= jc; ++kc) {
                    uint32_t a0 = hmul2(xp8[kc][0], s0);
                    uint32_t a1 = hmul2(xp8[kc][1], s1);
                    uint32_t a2 = hmul2(xp8[kc][2], s2);
                    uint32_t a3 = hmul2(xp8[kc][3], s3);
                    const uint32_t* wj = wsp + ((j * 4 + kc) * 4) * 32;
                    #pragma unroll
                    for (int nb = 0; nb < 4; ++nb) {
                        uint32_t b = wj[nb * 32];
                        mma8h(acc[0][nb], a0, a1, b);
                        mma8h(acc[1][nb], a2, a3, b);
                    }
                }
            }
        }

        // ---- store ----
        #pragma unroll
        for (int f = 0; f < 2; ++f) {
            float* o0 = out + ((size_t)t * 512 + rA + 16 * f) * 32 + 2 * q;
            float* o1 = o0 + 8 * 32;
            #pragma unroll
            for (int nb = 0; nb < 4; ++nb) {
                *reinterpret_cast<float2*>(o0 + nb * 8) =
                    make_float2(acc[f][nb][0], acc[f][nb][1]);
                *reinterpret_cast<float2*>(o1 + nb * 8) =
                    make_float2(acc[f][nb][2], acc[f][nb][3]);
            }
        }
        buf ^= 1;
    }
}

extern "C" void kernel_launch(void* const* d_in, const int* in_sizes, int n_in,
                              void* d_out, int out_size) {
    const float* x    = (const float*)d_in[0];
    const float* wlin = (const float*)d_in[1];
    const float* wnl  = (const float*)d_in[2];
    float* out = (float*)d_out;

    int ntiles = in_sizes[0] / 16384;       // 512-row tiles; 1024 for B=524288

    int dev = 0, sms = 148;
    cudaGetDevice(&dev);
    cudaDeviceGetAttribute(&sms, cudaDevAttrMultiProcessorCount, dev);
    if (sms <= 0) sms = 148;
    int grid = sms < ntiles ? sms : ntiles;

    cudaFuncSetAttribute(nnode_kernel, cudaFuncAttributeMaxDynamicSharedMemorySize, SMEM_BYTES);
    nnode_kernel<<<grid, THREADS, SMEM_BYTES>>>(x, wlin, wnl, out, ntiles);
}

// round 8
// speedup vs baseline: 1.5974x; 1.5974x over previous
#include <cuda_runtime.h>
#include <cuda_fp16.h>
#include <cstdint>

#define THREADS 512
// ---- shared memory layout (bytes) ----
#define WS_OFF    0                        // paired B~ frags: 8jj*5p*4nb*32ln*8B = 40960
#define WH_OFF    40960                    // W_lin hi k16 frags: 2kc*4nb*32*8 = 2048
#define WL_OFF    43008                    // W_lin lo k16 frags: 2048
#define XT_OFF    45056                    // two x tiles, 512 rows * 36 floats
#define XT_STRIDE 36
#define XT_BYTES  (512 * XT_STRIDE * 4)    // 73728
#define SMEM_BYTES (XT_OFF + 2 * XT_BYTES) // 192512

static __device__ __forceinline__ uint32_t smem_u32(const void* p) {
    uint32_t a;
    asm("{ .reg .u64 t; cvta.to.shared.u64 t, %1; cvt.u32.u64 %0, t; }" : "=r"(a) : "l"(p));
    return a;
}
static __device__ __forceinline__ uint32_t hsplat(float f) {
    uint32_t d; asm("cvt.rn.f16x2.f32 %0, %1, %1;" : "=r"(d) : "f"(f)); return d;
}
static __device__ __forceinline__ uint32_t hmul2(uint32_t a, uint32_t b) {
    uint32_t d; asm("mul.rn.f16x2 %0, %1, %2;" : "=r"(d) : "r"(a), "r"(b)); return d;
}
static __device__ __forceinline__ uint32_t hpack(float lo, float hi) {
    __half2 h = __floats2half2_rn(lo, hi);
    return *reinterpret_cast<uint32_t*>(&h);
}
static __device__ __forceinline__ void hsplit(float2 v, uint32_t& h, uint32_t& l) {
    __half2 hh = __floats2half2_rn(v.x, v.y);
    float2 b = __half22float2(hh);
    __half2 ll = __floats2half2_rn(v.x - b.x, v.y - b.y);
    h = *reinterpret_cast<uint32_t*>(&hh);
    l = *reinterpret_cast<uint32_t*>(&ll);
}
// f16 m16n8k16: D += A*B, fp32 accum
static __device__ __forceinline__ void mma16(float* acc, uint32_t a0, uint32_t a1,
                                             uint32_t a2, uint32_t a3,
                                             uint32_t b0, uint32_t b1) {
    asm volatile(
        "mma.sync.aligned.m16n8k16.row.col.f32.f16.f16.f32 "
        "{%0,%1,%2,%3}, {%4,%5,%6,%7}, {%8,%9}, {%0,%1,%2,%3};"
        : "+f"(acc[0]), "+f"(acc[1]), "+f"(acc[2]), "+f"(acc[3])
        : "r"(a0), "r"(a1), "r"(a2), "r"(a3), "r"(b0), "r"(b1));
}

// One packed bilinear step: cells (jA,kA)+(jB,kB) against paired B frag p.
static __device__ __forceinline__ void bpack(
    float acc[2][4][4], const uint2* wsp, int jj, int p,
    const uint32_t xp8[4][4], const uint32_t s[4][4],
    int jA, int kA, int jB, int kB)
{
    const uint2* wj = wsp + ((jj * 5 + p) * 4) * 32;
    #pragma unroll
    for (int f = 0; f < 2; ++f) {
        uint32_t a0 = hmul2(xp8[kA][2*f],   s[jA][2*f]);
        uint32_t a1 = hmul2(xp8[kA][2*f+1], s[jA][2*f+1]);
        uint32_t a2 = hmul2(xp8[kB][2*f],   s[jB][2*f]);
        uint32_t a3 = hmul2(xp8[kB][2*f+1], s[jB][2*f+1]);
        #pragma unroll
        for (int nb = 0; nb < 4; ++nb) {
            uint2 b = wj[nb * 32];
            mma16(acc[f][nb], a0, a1, a2, a3, b.x, b.y);
        }
    }
}

#define CP_ASYNC16(dst, src) \
    asm volatile("cp.async.cg.shared.global [%0], [%1], 16;" :: "r"(dst), "l"(src) : "memory")
#define CP_COMMIT() asm volatile("cp.async.commit_group;" ::: "memory")
#define CP_WAIT1()  asm volatile("cp.async.wait_group 1;" ::: "memory")
#define CP_WAIT0()  asm volatile("cp.async.wait_group 0;" ::: "memory")

extern __shared__ __align__(1024) char smem[];

__global__ void __launch_bounds__(THREADS, 1)
nnode_kernel(const float* __restrict__ x, const float* __restrict__ wlin,
             const float* __restrict__ wnl, float* __restrict__ out, int ntiles) {
    const uint32_t sb = smem_u32(smem);
    const int tid  = threadIdx.x;
    const int wid  = tid >> 5;
    const int lane = tid & 31;
    const int q    = lane & 3;
    const int g    = lane >> 2;
    const int grid = gridDim.x;

    // ===== build paired symmetrized B~ fragments =====
    // pairing per jj (j = jj + jg*8):
    //   p0: (jj+8, kc0; c=1)   + (jj+8, kc1; c=.5)
    //   p1: (jj+16,kc0; c=1)   + (jj+16,kc1; c=1)
    //   p2: (jj,  kc0; c=.5)   + (jj+16,kc2; c=.5)
    //   p3: (jj+24,kc0; c=1)   + (jj+24,kc1; c=1)
    //   p4: (jj+24,kc2; c=1)   + (jj+24,kc3; c=.5)
    // cell value = c*(W[n,i0,j]+W[n,j,i0]), i0 = kc*8+2*(ln&3), n = nb*8+(ln>>2)
    {
        const int   jgA[5] = {1, 2, 0, 3, 3};
        const int   kcA[5] = {0, 0, 0, 0, 2};
        const float cfA[5] = {1.f, 1.f, 0.5f, 1.f, 1.f};
        const int   jgB[5] = {1, 2, 2, 3, 3};
        const int   kcB[5] = {1, 1, 2, 1, 3};
        const float cfB[5] = {0.5f, 1.f, 0.5f, 1.f, 0.5f};
        uint2* ws = reinterpret_cast<uint2*>(smem + WS_OFF);
        for (int idx = tid; idx < 5120; idx += THREADS) {
            int ln = idx & 31;
            int nb = (idx >> 5) & 3;
            int rest = idx >> 7;
            int p  = rest % 5;
            int jj = rest / 5;
            int n  = nb * 8 + (ln >> 2);
            const float* wn = wnl + n * 1024;
            uint2 v;
            {
                int j = jj + jgA[p] * 8, i0 = kcA[p] * 8 + 2 * (ln & 3);
                float c = cfA[p];
                v.x = hpack(c * (__ldg(wn + i0 * 32 + j)       + __ldg(wn + j * 32 + i0)),
                            c * (__ldg(wn + (i0 + 1) * 32 + j) + __ldg(wn + j * 32 + i0 + 1)));
            }
            {
                int j = jj + jgB[p] * 8, i0 = kcB[p] * 8 + 2 * (ln & 3);
                float c = cfB[p];
                v.y = hpack(c * (__ldg(wn + i0 * 32 + j)       + __ldg(wn + j * 32 + i0)),
                            c * (__ldg(wn + (i0 + 1) * 32 + j) + __ldg(wn + j * 32 + i0 + 1)));
            }
            ws[idx] = v;
        }
    }
    // ===== W_lin hi/lo fp16 k16 fragments =====
    {
        uint2* wh = reinterpret_cast<uint2*>(smem + WH_OFF);
        uint2* wl = reinterpret_cast<uint2*>(smem + WL_OFF);
        for (int idx = tid; idx < 256; idx += THREADS) {
            int kc2 = idx >> 7;
            int nb  = (idx >> 5) & 3;
            int ln  = idx & 31;
            int n   = nb * 8 + (ln >> 2);
            int i0  = kc2 * 16 + 2 * (ln & 3);
            uint32_t h0, l0, h1, l1;
            hsplit(make_float2(__ldg(wlin + i0 * 32 + n), __ldg(wlin + (i0 + 1) * 32 + n)), h0, l0);
            hsplit(make_float2(__ldg(wlin + (i0 + 8) * 32 + n), __ldg(wlin + (i0 + 9) * 32 + n)), h1, l1);
            wh[idx] = make_uint2(h0, h1);
            wl[idx] = make_uint2(l0, l1);
        }
    }

    // ===== prefetch first 512-row x tile (16384 floats = 512thr*4*8) =====
    const int t0 = blockIdx.x;
    if (t0 < ntiles) {
        const float* src = x + (size_t)t0 * 16384;
        #pragma unroll
        for (int s = 0; s < 8; ++s) {
            int f = (tid + s * THREADS) * 4;
            int r = f >> 5, c = f & 31;
            CP_ASYNC16(sb + XT_OFF + (uint32_t)(r * XT_STRIDE + c) * 4, src + f);
        }
    }
    CP_COMMIT();

    const int rA = wid * 32 + g;
    const uint2* wsp = reinterpret_cast<const uint2*>(smem + WS_OFF) + lane;
    const uint2* whp = reinterpret_cast<const uint2*>(smem + WH_OFF) + lane;
    const uint2* wlp = reinterpret_cast<const uint2*>(smem + WL_OFF) + lane;

    int buf = 0;
    for (int t = t0; t < ntiles; t += grid) {
        __syncthreads();
        int tn = t + grid;
        if (tn < ntiles) {
            const float* src = x + (size_t)tn * 16384;
            uint32_t dst = sb + XT_OFF + (uint32_t)(buf ^ 1) * XT_BYTES;
            #pragma unroll
            for (int s = 0; s < 8; ++s) {
                int f = (tid + s * THREADS) * 4;
                int r = f >> 5, c = f & 31;
                CP_ASYNC16(dst + (uint32_t)(r * XT_STRIDE + c) * 4, src + f);
            }
            CP_COMMIT();
            CP_WAIT1();
        } else {
            CP_WAIT0();
        }
        __syncthreads();

        const float* xt  = reinterpret_cast<const float*>(smem + XT_OFF + buf * XT_BYTES);
        const float* xr[4] = { xt + (rA +  0) * XT_STRIDE, xt + (rA +  8) * XT_STRIDE,
                               xt + (rA + 16) * XT_STRIDE, xt + (rA + 24) * XT_STRIDE };

        // ---- packed fp16 hi + residual X fragments ----
        uint32_t xp8[4][4], xlp8[4][4];
        #pragma unroll
        for (int kc = 0; kc < 4; ++kc) {
            #pragma unroll
            for (int ridx = 0; ridx < 4; ++ridx)
                hsplit(*reinterpret_cast<const float2*>(xr[ridx] + kc * 8 + 2 * q),
                       xp8[kc][ridx], xlp8[kc][ridx]);
        }

        float acc[2][4][4];
        #pragma unroll
        for (int f = 0; f < 2; ++f)
            #pragma unroll
            for (int nb = 0; nb < 4; ++nb)
                #pragma unroll
                for (int e = 0; e < 4; ++e) acc[f][nb][e] = 0.f;

        // ---- linear term: hi@Wh + lo@Wh + hi@Wl (fp16 products exact in fp32) ----
        #pragma unroll
        for (int kc2 = 0; kc2 < 2; ++kc2) {
            #pragma unroll
            for (int nb = 0; nb < 4; ++nb) {
                uint2 bh = whp[(kc2 * 4 + nb) * 32];
                uint2 bl = wlp[(kc2 * 4 + nb) * 32];
                #pragma unroll
                for (int f = 0; f < 2; ++f) {
                    mma16(acc[f][nb], xp8[2*kc2][2*f],  xp8[2*kc2][2*f+1],
                                      xp8[2*kc2+1][2*f], xp8[2*kc2+1][2*f+1], bh.x, bh.y);
                    mma16(acc[f][nb], xlp8[2*kc2][2*f],  xlp8[2*kc2][2*f+1],
                                      xlp8[2*kc2+1][2*f], xlp8[2*kc2+1][2*f+1], bh.x, bh.y);
                    mma16(acc[f][nb], xp8[2*kc2][2*f],  xp8[2*kc2][2*f+1],
                                      xp8[2*kc2+1][2*f], xp8[2*kc2+1][2*f+1], bl.x, bl.y);
                }
            }
        }

        // ---- bilinear: 5 packed k16 mmas per jj, 40 total ----
        #pragma unroll 2
        for (int jj = 0; jj < 8; ++jj) {
            uint32_t s[4][4];                 // s[jgrp][ridx], j = jj + jgrp*8
            #pragma unroll
            for (int jg = 0; jg < 4; ++jg)
                #pragma unroll
                for (int ridx = 0; ridx < 4; ++ridx)
                    s[jg][ridx] = hsplat(xr[ridx][jj + jg * 8]);

            bpack(acc, wsp, jj, 0, xp8, s, 1, 0, 1, 1);
            bpack(acc, wsp, jj, 1, xp8, s, 2, 0, 2, 1);
            bpack(acc, wsp, jj, 2, xp8, s, 0, 0, 2, 2);
            bpack(acc, wsp, jj, 3, xp8, s, 3, 0, 3, 1);
            bpack(acc, wsp, jj, 4, xp8, s, 3, 2, 3, 3);
        }

        // ---- store ----
        #pragma unroll
        for (int f = 0; f < 2; ++f) {
            float* o0 = out + ((size_t)t * 512 + rA + 16 * f) * 32 + 2 * q;
            float* o1 = o0 + 8 * 32;
            #pragma unroll
            for (int nb = 0; nb < 4; ++nb) {
                *reinterpret_cast<float2*>(o0 + nb * 8) =
                    make_float2(acc[f][nb][0], acc[f][nb][1]);
                *reinterpret_cast<float2*>(o1 + nb * 8) =
                    make_float2(acc[f][nb][2], acc[f][nb][3]);
            }
        }
        buf ^= 1;
    }
}

extern "C" void kernel_launch(void* const* d_in, const int* in_sizes, int n_in,
                              void* d_out, int out_size) {
    const float* x    = (const float*)d_in[0];
    const float* wlin = (const float*)d_in[1];
    const float* wnl  = (const float*)d_in[2];
    float* out = (float*)d_out;

    int ntiles = in_sizes[0] / 16384;       // 512-row tiles; 1024 for B=524288

    int dev = 0, sms = 148;
    cudaGetDevice(&dev);
    cudaDeviceGetAttribute(&sms, cudaDevAttrMultiProcessorCount, dev);
    if (sms <= 0) sms = 148;
    int grid = sms < ntiles ? sms : ntiles;

    cudaFuncSetAttribute(nnode_kernel, cudaFuncAttributeMaxDynamicSharedMemorySize, SMEM_BYTES);
    nnode_kernel<<<grid, THREADS, SMEM_BYTES>>>(x, wlin, wnl, out, ntiles);
}